// round 2
// baseline (speedup 1.0000x reference)
#include <cuda_runtime.h>
#include <math.h>

#define MAXB 1024

// Scratch (no device allocs allowed): per-batch transform (A = M - I, 9 floats; t, 3 floats),
// per-batch error sums, and the two pose-loss scalars.
__device__ float g_A[MAXB * 12];
__device__ float g_sums[MAXB];
__device__ float g_pose[2];  // [0] = loss_transl, [1] = loss_rot

__device__ __forceinline__ void quat_to_rot(float qw, float qx, float qy, float qz, float* R) {
    float inv = rsqrtf(qw * qw + qx * qx + qy * qy + qz * qz);
    qw *= inv; qx *= inv; qy *= inv; qz *= inv;
    R[0] = 1.f - 2.f * (qy * qy + qz * qz);
    R[1] = 2.f * (qx * qy - qz * qw);
    R[2] = 2.f * (qx * qz + qy * qw);
    R[3] = 2.f * (qx * qy + qz * qw);
    R[4] = 1.f - 2.f * (qx * qx + qz * qz);
    R[5] = 2.f * (qy * qz - qx * qw);
    R[6] = 2.f * (qx * qz - qy * qw);
    R[7] = 2.f * (qy * qz + qx * qw);
    R[8] = 1.f - 2.f * (qx * qx + qy * qy);
}

// One block. Thread b handles batch b: builds A/t, computes pose-loss terms,
// zeroes the per-batch accumulator. Then block-reduces the pose terms.
__global__ void prologue_kernel(const float* __restrict__ tgt_t,
                                const float* __restrict__ tgt_r,
                                const float* __restrict__ err_t,
                                const float* __restrict__ err_r,
                                int B) {
    int b = threadIdx.x;
    float lt = 0.f, lr = 0.f;

    if (b < B) {
        g_sums[b] = 0.f;

        float Rt[9], Rp[9];
        quat_to_rot(tgt_r[4 * b + 0], tgt_r[4 * b + 1], tgt_r[4 * b + 2], tgt_r[4 * b + 3], Rt);
        quat_to_rot(err_r[4 * b + 0], err_r[4 * b + 1], err_r[4 * b + 2], err_r[4 * b + 3], Rp);

        // M = Rp^T * Rt ; t = Rp^T * (t_tgt - t_pred).  (RT_inv = inv(RT_pred) * RT_target)
        float C[9];
        #pragma unroll
        for (int i = 0; i < 3; i++)
            #pragma unroll
            for (int j = 0; j < 3; j++)
                C[i * 3 + j] = Rp[0 * 3 + i] * Rt[0 * 3 + j]
                             + Rp[1 * 3 + i] * Rt[1 * 3 + j]
                             + Rp[2 * 3 + i] * Rt[2 * 3 + j];

        float d0 = tgt_t[3 * b + 0] - err_t[3 * b + 0];
        float d1 = tgt_t[3 * b + 1] - err_t[3 * b + 1];
        float d2 = tgt_t[3 * b + 2] - err_t[3 * b + 2];
        float t0 = Rp[0] * d0 + Rp[3] * d1 + Rp[6] * d2;
        float t1 = Rp[1] * d0 + Rp[4] * d1 + Rp[7] * d2;
        float t2 = Rp[2] * d0 + Rp[5] * d1 + Rp[8] * d2;

        // Store A = M - I, t
        C[0] -= 1.f; C[4] -= 1.f; C[8] -= 1.f;
        #pragma unroll
        for (int k = 0; k < 9; k++) g_A[b * 12 + k] = C[k];
        g_A[b * 12 + 9]  = t0;
        g_A[b * 12 + 10] = t1;
        g_A[b * 12 + 11] = t2;

        // Smooth-L1 translation loss (sum over 3 components)
        #pragma unroll
        for (int k = 0; k < 3; k++) {
            float d = fabsf(err_t[3 * b + k] - tgt_t[3 * b + k]);
            lt += (d < 1.f) ? 0.5f * d * d : d - 0.5f;
        }

        // Quaternion angular distance (degrees), on RAW (unnormalized) quats, as reference does.
        float q0 = err_r[4 * b + 0], q1 = err_r[4 * b + 1], q2 = err_r[4 * b + 2], q3 = err_r[4 * b + 3];
        float r0 = tgt_r[4 * b + 0], r1 = -tgt_r[4 * b + 1], r2 = -tgt_r[4 * b + 2], r3 = -tgt_r[4 * b + 3];
        float w = q0 * r0 - q1 * r1 - q2 * r2 - q3 * r3;
        float x = q0 * r1 + q1 * r0 + q2 * r3 - q3 * r2;
        float y = q0 * r2 - q1 * r3 + q2 * r0 + q3 * r1;
        float z = q0 * r3 + q1 * r2 - q2 * r1 + q3 * r0;
        float angle = 2.f * atan2f(sqrtf(x * x + y * y + z * z), fabsf(w));
        lr = angle * (180.f / 3.14159265358979323846f);
    }

    __shared__ float sA[1024];
    __shared__ float sB[1024];
    sA[threadIdx.x] = lt;
    sB[threadIdx.x] = lr;
    __syncthreads();
    for (int s = blockDim.x >> 1; s > 0; s >>= 1) {
        if (threadIdx.x < s) {
            sA[threadIdx.x] += sA[threadIdx.x + s];
            sB[threadIdx.x] += sB[threadIdx.x + s];
        }
        __syncthreads();
    }
    if (threadIdx.x == 0) {
        g_pose[0] = sA[0] / (float)B;
        g_pose[1] = sB[0] / (float)B;
    }
}

// Streaming kernel: grid (blocksPerBatch, B). Reads x/y/z rows (homogeneous row == 1.0
// by construction, never touched). err = || (M - I) p + t ||. Per-batch sum via
// block reduce + atomicAdd.
__global__ void __launch_bounds__(256) pc_kernel(const float* __restrict__ pc, int N) {
    int b = blockIdx.y;
    const float* base = pc + (size_t)b * 4 * (size_t)N;

    // Load per-batch transform (12 floats, L2-resident)
    float a00 = g_A[b * 12 + 0], a01 = g_A[b * 12 + 1], a02 = g_A[b * 12 + 2];
    float a10 = g_A[b * 12 + 3], a11 = g_A[b * 12 + 4], a12 = g_A[b * 12 + 5];
    float a20 = g_A[b * 12 + 6], a21 = g_A[b * 12 + 7], a22 = g_A[b * 12 + 8];
    float t0  = g_A[b * 12 + 9], t1  = g_A[b * 12 + 10], t2 = g_A[b * 12 + 11];

    float acc = 0.f;

    if ((N & 3) == 0) {
        int nvec = N >> 2;
        const float4* X = (const float4*)(base);
        const float4* Y = (const float4*)(base + N);
        const float4* Z = (const float4*)(base + 2 * (size_t)N);
        for (int i = blockIdx.x * blockDim.x + threadIdx.x; i < nvec;
             i += gridDim.x * blockDim.x) {
            float4 x = X[i];
            float4 y = Y[i];
            float4 z = Z[i];
            {
                float dx = fmaf(a00, x.x, fmaf(a01, y.x, fmaf(a02, z.x, t0)));
                float dy = fmaf(a10, x.x, fmaf(a11, y.x, fmaf(a12, z.x, t1)));
                float dz = fmaf(a20, x.x, fmaf(a21, y.x, fmaf(a22, z.x, t2)));
                acc += sqrtf(dx * dx + dy * dy + dz * dz);
            }
            {
                float dx = fmaf(a00, x.y, fmaf(a01, y.y, fmaf(a02, z.y, t0)));
                float dy = fmaf(a10, x.y, fmaf(a11, y.y, fmaf(a12, z.y, t1)));
                float dz = fmaf(a20, x.y, fmaf(a21, y.y, fmaf(a22, z.y, t2)));
                acc += sqrtf(dx * dx + dy * dy + dz * dz);
            }
            {
                float dx = fmaf(a00, x.z, fmaf(a01, y.z, fmaf(a02, z.z, t0)));
                float dy = fmaf(a10, x.z, fmaf(a11, y.z, fmaf(a12, z.z, t1)));
                float dz = fmaf(a20, x.z, fmaf(a21, y.z, fmaf(a22, z.z, t2)));
                acc += sqrtf(dx * dx + dy * dy + dz * dz);
            }
            {
                float dx = fmaf(a00, x.w, fmaf(a01, y.w, fmaf(a02, z.w, t0)));
                float dy = fmaf(a10, x.w, fmaf(a11, y.w, fmaf(a12, z.w, t1)));
                float dz = fmaf(a20, x.w, fmaf(a21, y.w, fmaf(a22, z.w, t2)));
                acc += sqrtf(dx * dx + dy * dy + dz * dz);
            }
        }
    } else {
        for (int n = blockIdx.x * blockDim.x + threadIdx.x; n < N;
             n += gridDim.x * blockDim.x) {
            float px = base[n], py = base[N + n], pz = base[2 * (size_t)N + n];
            float dx = fmaf(a00, px, fmaf(a01, py, fmaf(a02, pz, t0)));
            float dy = fmaf(a10, px, fmaf(a11, py, fmaf(a12, pz, t1)));
            float dz = fmaf(a20, px, fmaf(a21, py, fmaf(a22, pz, t2)));
            acc += sqrtf(dx * dx + dy * dy + dz * dz);
        }
    }

    // Block reduction
    __shared__ float s[256];
    s[threadIdx.x] = acc;
    __syncthreads();
    for (int st = blockDim.x >> 1; st >= 32; st >>= 1) {
        if (threadIdx.x < st) s[threadIdx.x] += s[threadIdx.x + st];
        __syncthreads();
    }
    if (threadIdx.x < 32) {
        float v = s[threadIdx.x];
        #pragma unroll
        for (int off = 16; off > 0; off >>= 1)
            v += __shfl_down_sync(0xFFFFFFFFu, v, off);
        if (threadIdx.x == 0) atomicAdd(&g_sums[b], v);
    }
}

__global__ void epilogue_kernel(float* __restrict__ out, int B, int N) {
    __shared__ float s[256];
    float v = 0.f;
    for (int b = threadIdx.x; b < B; b += blockDim.x)
        v += g_sums[b] / (float)N;
    s[threadIdx.x] = v;
    __syncthreads();
    for (int st = blockDim.x >> 1; st > 0; st >>= 1) {
        if (threadIdx.x < st) s[threadIdx.x] += s[threadIdx.x + st];
        __syncthreads();
    }
    if (threadIdx.x == 0) {
        float pc_loss = s[0];                 // sum over batches of per-batch mean
        float loss_transl = g_pose[0];
        float loss_rot = g_pose[1];
        float pose_loss = 1.0f * loss_transl + 1.0f * loss_rot;  // RESCALE_TRANS/ROT = 1
        float pcl_over_B = pc_loss / (float)B;
        out[0] = 0.5f * pose_loss + 0.5f * pcl_over_B;  // WEIGHT_PC = 0.5
        out[1] = loss_transl;
        out[2] = loss_rot;
        out[3] = pcl_over_B;
    }
}

extern "C" void kernel_launch(void* const* d_in, const int* in_sizes, int n_in,
                              void* d_out, int out_size) {
    const float* pc = (const float*)d_in[0];      // [B,4,N]
    const float* tt = (const float*)d_in[1];      // [B,3]
    const float* tr = (const float*)d_in[2];      // [B,4]
    const float* te = (const float*)d_in[3];      // [B,3]
    const float* re = (const float*)d_in[4];      // [B,4]

    int B = in_sizes[1] / 3;
    int N = in_sizes[0] / (4 * B);

    prologue_kernel<<<1, 1024>>>(tt, tr, te, re, B);

    int nvec = (N + 3) >> 2;
    int blocksPerBatch = (nvec + 255) / 256;
    if (blocksPerBatch > 64) blocksPerBatch = 64;
    if (blocksPerBatch < 1) blocksPerBatch = 1;
    dim3 grid(blocksPerBatch, B);
    pc_kernel<<<grid, 256>>>(pc, N);

    epilogue_kernel<<<1, 256>>>((float*)d_out, B, N);
}